// round 9
// baseline (speedup 1.0000x reference)
#include <cuda_runtime.h>

#define NN 50000
#define KK 15
#define DD 128
#define HH 64
#define NKE (NN*KK)

// Precomputed per-node projections (device globals — no allocation allowed).
__device__ float g_hdst[NN*64];   // x @ ew1[0:128]   + eb1
__device__ float g_hsrc[NN*64];   // x @ ew1[128:256]
__device__ float g_gdeg[NN*64];   // x @ dw1[0:128]   + db1

// ---------------------------------------------------------------------------
// Kernel A: three fused 50k x 128 @ 128x64 projections of x.
// 256 threads; warp = 4 nodes; x rows held in registers, broadcast via shfl.
// 99.2 KB smem -> 2 blocks/SM (16 warps), FMA-bound.
// ---------------------------------------------------------------------------
__global__ __launch_bounds__(256)
void precompute_kernel(const float* __restrict__ x,
                       const float* __restrict__ ew1, const float* __restrict__ eb1,
                       const float* __restrict__ dw1, const float* __restrict__ db1)
{
    extern __shared__ float s[];
    float* E1d = s;              // 128*64
    float* E1s = E1d + 8192;     // 128*64
    float* D1  = E1s + 8192;     // 128*64
    float* be  = D1 + 8192;      // 64
    float* bd  = be + 64;        // 64

    const int tid = threadIdx.x;
    const int wid = tid >> 5;
    const int lid = tid & 31;

    for (int i = tid; i < 8192; i += 256) {
        E1d[i] = ew1[i];
        E1s[i] = ew1[8192 + i];
        D1[i]  = dw1[i];
    }
    if (tid < 64) { be[tid] = eb1[tid]; bd[tid] = db1[tid]; }
    __syncthreads();

    for (int base = blockIdx.x*32 + wid*4; base < NN; base += gridDim.x*32) {
        // lane holds x[n][4*lid .. 4*lid+3] for each of 4 nodes
        float xr[4][4];
        #pragma unroll
        for (int m = 0; m < 4; m++) {
            int n = (base + m < NN) ? base + m : NN - 1;
            float4 v = ((const float4*)(x + (size_t)n*DD))[lid];
            xr[m][0] = v.x; xr[m][1] = v.y; xr[m][2] = v.z; xr[m][3] = v.w;
        }

        float a0[4], a1[4], a2[4], a3[4], a4[4], a5[4];
        #pragma unroll
        for (int m = 0; m < 4; m++) {
            a0[m] = be[lid]; a1[m] = be[32+lid];
            a2[m] = 0.f;     a3[m] = 0.f;
            a4[m] = bd[lid]; a5[m] = bd[32+lid];
        }

        #pragma unroll 2
        for (int kq = 0; kq < 32; kq++) {
            #pragma unroll
            for (int j = 0; j < 4; j++) {
                const int k = kq*4 + j;
                float b0 = __shfl_sync(0xffffffffu, xr[0][j], kq);
                float b1 = __shfl_sync(0xffffffffu, xr[1][j], kq);
                float b2 = __shfl_sync(0xffffffffu, xr[2][j], kq);
                float b3v = __shfl_sync(0xffffffffu, xr[3][j], kq);
                float w0 = E1d[k*64 + lid], w1 = E1d[k*64 + 32 + lid];
                float w2 = E1s[k*64 + lid], w3 = E1s[k*64 + 32 + lid];
                float w4 = D1[k*64 + lid],  w5 = D1[k*64 + 32 + lid];
                a0[0] = fmaf(b0, w0, a0[0]); a1[0] = fmaf(b0, w1, a1[0]);
                a2[0] = fmaf(b0, w2, a2[0]); a3[0] = fmaf(b0, w3, a3[0]);
                a4[0] = fmaf(b0, w4, a4[0]); a5[0] = fmaf(b0, w5, a5[0]);
                a0[1] = fmaf(b1, w0, a0[1]); a1[1] = fmaf(b1, w1, a1[1]);
                a2[1] = fmaf(b1, w2, a2[1]); a3[1] = fmaf(b1, w3, a3[1]);
                a4[1] = fmaf(b1, w4, a4[1]); a5[1] = fmaf(b1, w5, a5[1]);
                a0[2] = fmaf(b2, w0, a0[2]); a1[2] = fmaf(b2, w1, a1[2]);
                a2[2] = fmaf(b2, w2, a2[2]); a3[2] = fmaf(b2, w3, a3[2]);
                a4[2] = fmaf(b2, w4, a4[2]); a5[2] = fmaf(b2, w5, a5[2]);
                a0[3] = fmaf(b3v, w0, a0[3]); a1[3] = fmaf(b3v, w1, a1[3]);
                a2[3] = fmaf(b3v, w2, a2[3]); a3[3] = fmaf(b3v, w3, a3[3]);
                a4[3] = fmaf(b3v, w4, a4[3]); a5[3] = fmaf(b3v, w5, a5[3]);
            }
        }

        #pragma unroll
        for (int m = 0; m < 4; m++) {
            int n = base + m;
            if (n >= NN) continue;
            size_t o = (size_t)n * 64;
            g_hdst[o + lid] = a0[m]; g_hdst[o + 32 + lid] = a1[m];
            g_hsrc[o + lid] = a2[m]; g_hsrc[o + 32 + lid] = a3[m];
            g_gdeg[o + lid] = a4[m]; g_gdeg[o + 32 + lid] = a5[m];
        }
    }
}

// ---------------------------------------------------------------------------
// Kernel B (fused): warp = one node (all 15 edges + node MLP + gating).
// Edge layer 1 = gathered precomputed rows; layer 2 = 64x64 vs SMEM weights
// (60 FFMA per 19 LDS). Butterfly reduce gives every lane all 15 logits, so
// the same warp finishes energies, degree hint, degree MLP, rank gate,
// and normalization — no global round-trip, no third kernel.
// ---------------------------------------------------------------------------
__global__ __launch_bounds__(256)
void fused_kernel(const int* __restrict__ eidx,
                  const float* __restrict__ edist,
                  const float* __restrict__ ew1,
                  const float* __restrict__ ew2, const float* __restrict__ eb2,
                  const float* __restrict__ ew3, const float* __restrict__ eb3,
                  const float* __restrict__ dw1,
                  const float* __restrict__ dw2, const float* __restrict__ db2,
                  const float* __restrict__ dw3, const float* __restrict__ db3,
                  float* __restrict__ out_w, float* __restrict__ out_g,
                  float* __restrict__ out_e, float* __restrict__ out_k)
{
    extern __shared__ float s[];
    float* W2s  = s;              // 64*64  edge layer-2
    float* D2s  = W2s + 4096;     // 64*64  degree layer-2
    float* w256 = D2s + 4096;     // 64     ew1 row 256 (dist weights)
    float* b2s  = w256 + 64;      // 64
    float* W3e  = b2s + 64;       // 64
    float* dwh  = W3e + 64;       // 64     dw1 row 128 (hint weights)
    float* b2d  = dwh + 64;       // 64
    float* W3d  = b2d + 64;       // 64
    float* tiles = W3d + 64;      // 8 warps * 1024

    const int tid = threadIdx.x;
    const int wid = tid >> 5;
    const int lid = tid & 31;

    for (int i = tid; i < 4096; i += 256) { W2s[i] = ew2[i]; D2s[i] = dw2[i]; }
    if (tid < 64) {
        w256[tid] = ew1[256*64 + tid]; b2s[tid] = eb2[tid]; W3e[tid] = ew3[tid];
        dwh[tid]  = dw1[128*64 + tid]; b2d[tid] = db2[tid]; W3d[tid] = dw3[tid];
    }
    const float b3e = eb3[0];
    const float b3d = db3[0];
    __syncthreads();

    float* tile = tiles + wid * 1024;
    float* es   = tile + 960;            // last 64 floats: energy scratch

    for (int node = blockIdx.x*8 + wid; node < NN; node += gridDim.x*8) {
        // ---- edge layer 1: gather precomputed projections ----
        const float2 hd  = *(const float2*)(g_hdst + (size_t)node*64 + lid*2);
        const float2 w2v = *(const float2*)(w256 + lid*2);
        #pragma unroll
        for (int m = 0; m < KK; m++) {
            int src = __ldg(eidx + node*KK + m);
            float2 hsv = *(const float2*)(g_hsrc + (size_t)src*64 + lid*2);
            float  dm  = __ldg(edist + node*KK + m);
            float h0 = fmaxf(fmaf(dm, w2v.x, hd.x + hsv.x), 0.f);
            float h1 = fmaxf(fmaf(dm, w2v.y, hd.y + hsv.y), 0.f);
            *(float2*)(tile + m*64 + lid*2) = make_float2(h0, h1);
        }
        __syncwarp();

        // ---- edge layer 2: 15 edges x 64 hidden ----
        float acc0[KK], acc1[KK];
        #pragma unroll
        for (int m = 0; m < KK; m++) { acc0[m] = b2s[lid]; acc1[m] = b2s[32+lid]; }
        #pragma unroll 2
        for (int k = 0; k < 64; k += 2) {
            float w00 = W2s[k*64 + lid],     w01 = W2s[k*64 + 32 + lid];
            float w10 = W2s[(k+1)*64 + lid], w11 = W2s[(k+1)*64 + 32 + lid];
            #pragma unroll
            for (int m = 0; m < KK; m++) {
                float2 f = *(const float2*)(tile + m*64 + k);
                acc0[m] = fmaf(f.x, w00, acc0[m]); acc1[m] = fmaf(f.x, w01, acc1[m]);
                acc0[m] = fmaf(f.y, w10, acc0[m]); acc1[m] = fmaf(f.y, w11, acc1[m]);
            }
        }

        // ---- edge layer 3 + butterfly (all lanes get all 15 logits) ----
        const float w3a = W3e[lid], w3b = W3e[32 + lid];
        float p[KK];
        #pragma unroll
        for (int m = 0; m < KK; m++)
            p[m] = fmaxf(acc0[m], 0.f)*w3a + fmaxf(acc1[m], 0.f)*w3b;
        #pragma unroll
        for (int off = 16; off; off >>= 1) {
            #pragma unroll
            for (int m = 0; m < KK; m++)
                p[m] += __shfl_xor_sync(0xffffffffu, p[m], off);
        }

        // lane m takes logit m  (static select chain, no dynamic indexing)
        float pm = p[0];
        #pragma unroll
        for (int m = 1; m < KK; m++) pm = (lid == m) ? p[m] : pm;
        float E = 0.f;
        if (lid < KK) {
            E = 1.f / (1.f + expf(-2.f * (pm + b3e)));   // sigmoid(logit/0.5)
            es[lid] = E;
            out_e[node*KK + lid] = E;
        }
        __syncwarp();

        // ---- degree hint + degree MLP layer 1 (precomputed gdeg) ----
        float hint = 0.f;
        #pragma unroll
        for (int j = 0; j < KK; j++) hint += es[j];
        const float2 gd  = *(const float2*)(g_gdeg + (size_t)node*64 + lid*2);
        const float2 dhv = *(const float2*)(dwh + lid*2);
        float a0 = fmaxf(fmaf(hint, dhv.x, gd.x), 0.f);
        float a1 = fmaxf(fmaf(hint, dhv.y, gd.y), 0.f);
        *(float2*)(tile + lid*2) = make_float2(a0, a1);
        __syncwarp();

        // ---- degree layer 2 + 3 -> k_cont ----
        float c0 = b2d[lid], c1 = b2d[32 + lid];
        #pragma unroll 4
        for (int k = 0; k < 64; k += 2) {
            float2 f = *(const float2*)(tile + k);
            c0 = fmaf(f.x, D2s[k*64 + lid],          c0);
            c1 = fmaf(f.x, D2s[k*64 + 32 + lid],     c1);
            c0 = fmaf(f.y, D2s[(k+1)*64 + lid],      c0);
            c1 = fmaf(f.y, D2s[(k+1)*64 + 32 + lid], c1);
        }
        float pk = fmaxf(c0, 0.f)*W3d[lid] + fmaxf(c1, 0.f)*W3d[32 + lid];
        #pragma unroll
        for (int off = 16; off; off >>= 1) pk += __shfl_xor_sync(0xffffffffu, pk, off);
        const float kcont = 2.0f + 13.0f / (1.f + expf(-(pk + b3d)));
        if (lid == 0) out_k[node] = kcont;

        // ---- hard top-k gate via rank (stable ties by index) + normalize ----
        float kint = rintf(kcont);
        kint = fminf(fmaxf(kint, 2.f), 15.f);
        int cnt = 0;
        #pragma unroll
        for (int j = 0; j < KK; j++) {
            float Ej = es[j];
            cnt += (Ej > E) || (Ej == E && j < lid);
        }
        const float gate = ((float)(cnt + 1) <= kint) ? 1.f : 0.f;
        const float wgt  = (lid < KK) ? E * gate : 0.f;
        float denom = wgt;
        #pragma unroll
        for (int off = 16; off; off >>= 1) denom += __shfl_xor_sync(0xffffffffu, denom, off);
        denom = fmaxf(denom, 1e-12f);
        if (lid < KK) {
            out_g[node*KK + lid] = gate;
            out_w[node*KK + lid] = wgt / denom;
        }
        __syncwarp();
    }
}

extern "C" void kernel_launch(void* const* d_in, const int* in_sizes, int n_in,
                              void* d_out, int out_size)
{
    const float* x     = (const float*)d_in[0];
    const int*   eidx  = (const int*)d_in[1];    // int32 (JAX x64 disabled); row 0 = src
    const float* edist = (const float*)d_in[2];
    const float* ew1   = (const float*)d_in[3];
    const float* eb1   = (const float*)d_in[4];
    const float* ew2   = (const float*)d_in[5];
    const float* eb2   = (const float*)d_in[6];
    const float* ew3   = (const float*)d_in[7];
    const float* eb3   = (const float*)d_in[8];
    const float* dw1   = (const float*)d_in[9];
    const float* db1   = (const float*)d_in[10];
    const float* dw2   = (const float*)d_in[11];
    const float* db2   = (const float*)d_in[12];
    const float* dw3   = (const float*)d_in[13];
    const float* db3   = (const float*)d_in[14];

    float* out   = (float*)d_out;
    float* out_w = out;               // edge_weight  (N*K)
    float* out_g = out + NKE;         // edge_gate    (N*K)
    float* out_e = out + 2*NKE;       // edge_energy  (N*K)
    float* out_k = out + 3*NKE;       // k_cont       (N)

    const int smemA = (3*8192 + 128) * 4;                       //  99,072 B -> 2 blocks/SM
    const int smemB = (2*4096 + 6*64 + 8*1024) * 4;             //  67,072 B -> 3 blocks/SM
    cudaFuncSetAttribute(precompute_kernel, cudaFuncAttributeMaxDynamicSharedMemorySize, smemA);
    cudaFuncSetAttribute(fused_kernel,      cudaFuncAttributeMaxDynamicSharedMemorySize, smemB);

    precompute_kernel<<<296, 256, smemA>>>(x, ew1, eb1, dw1, db1);
    fused_kernel<<<444, 256, smemB>>>(eidx, edist, ew1, ew2, eb2, ew3, eb3,
                                      dw1, dw2, db2, dw3, db3,
                                      out_w, out_g, out_e, out_k);
}

// round 10
// speedup vs baseline: 1.0024x; 1.0024x over previous
#include <cuda_runtime.h>

#define NN 50000
#define KK 15
#define DD 128
#define HH 64
#define NKE (NN*KK)

// Precomputed per-node projections (device globals — no allocation allowed).
__device__ float g_hdst[NN*64];   // x @ ew1[0:128]   + eb1
__device__ float g_hsrc[NN*64];   // x @ ew1[128:256]
__device__ float g_gdeg[NN*64];   // x @ dw1[0:128]   + db1

// ---------------------------------------------------------------------------
// Kernel A: three fused 50k x 128 @ 128x64 projections of x.
// 256 threads; warp = 4 nodes; x rows held in registers, broadcast via shfl.
// 99.2 KB smem -> 2 blocks/SM (16 warps), FMA-bound.
// ---------------------------------------------------------------------------
__global__ __launch_bounds__(256)
void precompute_kernel(const float* __restrict__ x,
                       const float* __restrict__ ew1, const float* __restrict__ eb1,
                       const float* __restrict__ dw1, const float* __restrict__ db1)
{
    extern __shared__ float s[];
    float* E1d = s;              // 128*64
    float* E1s = E1d + 8192;     // 128*64
    float* D1  = E1s + 8192;     // 128*64
    float* be  = D1 + 8192;      // 64
    float* bd  = be + 64;        // 64

    const int tid = threadIdx.x;
    const int wid = tid >> 5;
    const int lid = tid & 31;

    for (int i = tid; i < 8192; i += 256) {
        E1d[i] = ew1[i];
        E1s[i] = ew1[8192 + i];
        D1[i]  = dw1[i];
    }
    if (tid < 64) { be[tid] = eb1[tid]; bd[tid] = db1[tid]; }
    __syncthreads();

    for (int base = blockIdx.x*32 + wid*4; base < NN; base += gridDim.x*32) {
        // lane holds x[n][4*lid .. 4*lid+3] for each of 4 nodes
        float xr[4][4];
        #pragma unroll
        for (int m = 0; m < 4; m++) {
            int n = (base + m < NN) ? base + m : NN - 1;
            float4 v = ((const float4*)(x + (size_t)n*DD))[lid];
            xr[m][0] = v.x; xr[m][1] = v.y; xr[m][2] = v.z; xr[m][3] = v.w;
        }

        float a0[4], a1[4], a2[4], a3[4], a4[4], a5[4];
        #pragma unroll
        for (int m = 0; m < 4; m++) {
            a0[m] = be[lid]; a1[m] = be[32+lid];
            a2[m] = 0.f;     a3[m] = 0.f;
            a4[m] = bd[lid]; a5[m] = bd[32+lid];
        }

        #pragma unroll 2
        for (int kq = 0; kq < 32; kq++) {
            #pragma unroll
            for (int j = 0; j < 4; j++) {
                const int k = kq*4 + j;
                float b0 = __shfl_sync(0xffffffffu, xr[0][j], kq);
                float b1 = __shfl_sync(0xffffffffu, xr[1][j], kq);
                float b2 = __shfl_sync(0xffffffffu, xr[2][j], kq);
                float b3v = __shfl_sync(0xffffffffu, xr[3][j], kq);
                float w0 = E1d[k*64 + lid], w1 = E1d[k*64 + 32 + lid];
                float w2 = E1s[k*64 + lid], w3 = E1s[k*64 + 32 + lid];
                float w4 = D1[k*64 + lid],  w5 = D1[k*64 + 32 + lid];
                a0[0] = fmaf(b0, w0, a0[0]); a1[0] = fmaf(b0, w1, a1[0]);
                a2[0] = fmaf(b0, w2, a2[0]); a3[0] = fmaf(b0, w3, a3[0]);
                a4[0] = fmaf(b0, w4, a4[0]); a5[0] = fmaf(b0, w5, a5[0]);
                a0[1] = fmaf(b1, w0, a0[1]); a1[1] = fmaf(b1, w1, a1[1]);
                a2[1] = fmaf(b1, w2, a2[1]); a3[1] = fmaf(b1, w3, a3[1]);
                a4[1] = fmaf(b1, w4, a4[1]); a5[1] = fmaf(b1, w5, a5[1]);
                a0[2] = fmaf(b2, w0, a0[2]); a1[2] = fmaf(b2, w1, a1[2]);
                a2[2] = fmaf(b2, w2, a2[2]); a3[2] = fmaf(b2, w3, a3[2]);
                a4[2] = fmaf(b2, w4, a4[2]); a5[2] = fmaf(b2, w5, a5[2]);
                a0[3] = fmaf(b3v, w0, a0[3]); a1[3] = fmaf(b3v, w1, a1[3]);
                a2[3] = fmaf(b3v, w2, a2[3]); a3[3] = fmaf(b3v, w3, a3[3]);
                a4[3] = fmaf(b3v, w4, a4[3]); a5[3] = fmaf(b3v, w5, a5[3]);
            }
        }

        #pragma unroll
        for (int m = 0; m < 4; m++) {
            int n = base + m;
            if (n >= NN) continue;
            size_t o = (size_t)n * 64;
            g_hdst[o + lid] = a0[m]; g_hdst[o + 32 + lid] = a1[m];
            g_hsrc[o + lid] = a2[m]; g_hsrc[o + 32 + lid] = a3[m];
            g_gdeg[o + lid] = a4[m]; g_gdeg[o + 32 + lid] = a5[m];
        }
    }
}

// ---------------------------------------------------------------------------
// Kernel B (fused): warp = one node (all 15 edges + node MLP + gating).
// Edge layer 1 = gathered precomputed rows; layer 2 = 64x64 vs SMEM weights
// (60 FFMA per 19 LDS). Butterfly reduce gives every lane all 15 logits, so
// the same warp finishes energies, degree hint, degree MLP, rank gate,
// and normalization — no global round-trip, no third kernel.
// ---------------------------------------------------------------------------
__global__ __launch_bounds__(256)
void fused_kernel(const int* __restrict__ eidx,
                  const float* __restrict__ edist,
                  const float* __restrict__ ew1,
                  const float* __restrict__ ew2, const float* __restrict__ eb2,
                  const float* __restrict__ ew3, const float* __restrict__ eb3,
                  const float* __restrict__ dw1,
                  const float* __restrict__ dw2, const float* __restrict__ db2,
                  const float* __restrict__ dw3, const float* __restrict__ db3,
                  float* __restrict__ out_w, float* __restrict__ out_g,
                  float* __restrict__ out_e, float* __restrict__ out_k)
{
    extern __shared__ float s[];
    float* W2s  = s;              // 64*64  edge layer-2
    float* D2s  = W2s + 4096;     // 64*64  degree layer-2
    float* w256 = D2s + 4096;     // 64     ew1 row 256 (dist weights)
    float* b2s  = w256 + 64;      // 64
    float* W3e  = b2s + 64;       // 64
    float* dwh  = W3e + 64;       // 64     dw1 row 128 (hint weights)
    float* b2d  = dwh + 64;       // 64
    float* W3d  = b2d + 64;       // 64
    float* tiles = W3d + 64;      // 8 warps * 1024

    const int tid = threadIdx.x;
    const int wid = tid >> 5;
    const int lid = tid & 31;

    for (int i = tid; i < 4096; i += 256) { W2s[i] = ew2[i]; D2s[i] = dw2[i]; }
    if (tid < 64) {
        w256[tid] = ew1[256*64 + tid]; b2s[tid] = eb2[tid]; W3e[tid] = ew3[tid];
        dwh[tid]  = dw1[128*64 + tid]; b2d[tid] = db2[tid]; W3d[tid] = dw3[tid];
    }
    const float b3e = eb3[0];
    const float b3d = db3[0];
    __syncthreads();

    float* tile = tiles + wid * 1024;
    float* es   = tile + 960;            // last 64 floats: energy scratch

    for (int node = blockIdx.x*8 + wid; node < NN; node += gridDim.x*8) {
        // ---- edge layer 1: gather precomputed projections ----
        const float2 hd  = *(const float2*)(g_hdst + (size_t)node*64 + lid*2);
        const float2 w2v = *(const float2*)(w256 + lid*2);
        #pragma unroll
        for (int m = 0; m < KK; m++) {
            int src = __ldg(eidx + node*KK + m);
            float2 hsv = *(const float2*)(g_hsrc + (size_t)src*64 + lid*2);
            float  dm  = __ldg(edist + node*KK + m);
            float h0 = fmaxf(fmaf(dm, w2v.x, hd.x + hsv.x), 0.f);
            float h1 = fmaxf(fmaf(dm, w2v.y, hd.y + hsv.y), 0.f);
            *(float2*)(tile + m*64 + lid*2) = make_float2(h0, h1);
        }
        __syncwarp();

        // ---- edge layer 2: 15 edges x 64 hidden ----
        float acc0[KK], acc1[KK];
        #pragma unroll
        for (int m = 0; m < KK; m++) { acc0[m] = b2s[lid]; acc1[m] = b2s[32+lid]; }
        #pragma unroll 2
        for (int k = 0; k < 64; k += 2) {
            float w00 = W2s[k*64 + lid],     w01 = W2s[k*64 + 32 + lid];
            float w10 = W2s[(k+1)*64 + lid], w11 = W2s[(k+1)*64 + 32 + lid];
            #pragma unroll
            for (int m = 0; m < KK; m++) {
                float2 f = *(const float2*)(tile + m*64 + k);
                acc0[m] = fmaf(f.x, w00, acc0[m]); acc1[m] = fmaf(f.x, w01, acc1[m]);
                acc0[m] = fmaf(f.y, w10, acc0[m]); acc1[m] = fmaf(f.y, w11, acc1[m]);
            }
        }

        // ---- edge layer 3 + butterfly (all lanes get all 15 logits) ----
        const float w3a = W3e[lid], w3b = W3e[32 + lid];
        float p[KK];
        #pragma unroll
        for (int m = 0; m < KK; m++)
            p[m] = fmaxf(acc0[m], 0.f)*w3a + fmaxf(acc1[m], 0.f)*w3b;
        #pragma unroll
        for (int off = 16; off; off >>= 1) {
            #pragma unroll
            for (int m = 0; m < KK; m++)
                p[m] += __shfl_xor_sync(0xffffffffu, p[m], off);
        }

        // lane m takes logit m  (static select chain, no dynamic indexing)
        float pm = p[0];
        #pragma unroll
        for (int m = 1; m < KK; m++) pm = (lid == m) ? p[m] : pm;
        float E = 0.f;
        if (lid < KK) {
            E = 1.f / (1.f + expf(-2.f * (pm + b3e)));   // sigmoid(logit/0.5)
            es[lid] = E;
            out_e[node*KK + lid] = E;
        }
        __syncwarp();

        // ---- degree hint + degree MLP layer 1 (precomputed gdeg) ----
        float hint = 0.f;
        #pragma unroll
        for (int j = 0; j < KK; j++) hint += es[j];
        const float2 gd  = *(const float2*)(g_gdeg + (size_t)node*64 + lid*2);
        const float2 dhv = *(const float2*)(dwh + lid*2);
        float a0 = fmaxf(fmaf(hint, dhv.x, gd.x), 0.f);
        float a1 = fmaxf(fmaf(hint, dhv.y, gd.y), 0.f);
        *(float2*)(tile + lid*2) = make_float2(a0, a1);
        __syncwarp();

        // ---- degree layer 2 + 3 -> k_cont ----
        float c0 = b2d[lid], c1 = b2d[32 + lid];
        #pragma unroll 4
        for (int k = 0; k < 64; k += 2) {
            float2 f = *(const float2*)(tile + k);
            c0 = fmaf(f.x, D2s[k*64 + lid],          c0);
            c1 = fmaf(f.x, D2s[k*64 + 32 + lid],     c1);
            c0 = fmaf(f.y, D2s[(k+1)*64 + lid],      c0);
            c1 = fmaf(f.y, D2s[(k+1)*64 + 32 + lid], c1);
        }
        float pk = fmaxf(c0, 0.f)*W3d[lid] + fmaxf(c1, 0.f)*W3d[32 + lid];
        #pragma unroll
        for (int off = 16; off; off >>= 1) pk += __shfl_xor_sync(0xffffffffu, pk, off);
        const float kcont = 2.0f + 13.0f / (1.f + expf(-(pk + b3d)));
        if (lid == 0) out_k[node] = kcont;

        // ---- hard top-k gate via rank (stable ties by index) + normalize ----
        float kint = rintf(kcont);
        kint = fminf(fmaxf(kint, 2.f), 15.f);
        int cnt = 0;
        #pragma unroll
        for (int j = 0; j < KK; j++) {
            float Ej = es[j];
            cnt += (Ej > E) || (Ej == E && j < lid);
        }
        const float gate = ((float)(cnt + 1) <= kint) ? 1.f : 0.f;
        const float wgt  = (lid < KK) ? E * gate : 0.f;
        float denom = wgt;
        #pragma unroll
        for (int off = 16; off; off >>= 1) denom += __shfl_xor_sync(0xffffffffu, denom, off);
        denom = fmaxf(denom, 1e-12f);
        if (lid < KK) {
            out_g[node*KK + lid] = gate;
            out_w[node*KK + lid] = wgt / denom;
        }
        __syncwarp();
    }
}

extern "C" void kernel_launch(void* const* d_in, const int* in_sizes, int n_in,
                              void* d_out, int out_size)
{
    const float* x     = (const float*)d_in[0];
    const int*   eidx  = (const int*)d_in[1];    // int32 (JAX x64 disabled); row 0 = src
    const float* edist = (const float*)d_in[2];
    const float* ew1   = (const float*)d_in[3];
    const float* eb1   = (const float*)d_in[4];
    const float* ew2   = (const float*)d_in[5];
    const float* eb2   = (const float*)d_in[6];
    const float* ew3   = (const float*)d_in[7];
    const float* eb3   = (const float*)d_in[8];
    const float* dw1   = (const float*)d_in[9];
    const float* db1   = (const float*)d_in[10];
    const float* dw2   = (const float*)d_in[11];
    const float* db2   = (const float*)d_in[12];
    const float* dw3   = (const float*)d_in[13];
    const float* db3   = (const float*)d_in[14];

    float* out   = (float*)d_out;
    float* out_w = out;               // edge_weight  (N*K)
    float* out_g = out + NKE;         // edge_gate    (N*K)
    float* out_e = out + 2*NKE;       // edge_energy  (N*K)
    float* out_k = out + 3*NKE;       // k_cont       (N)

    const int smemA = (3*8192 + 128) * 4;                       //  99,072 B -> 2 blocks/SM
    const int smemB = (2*4096 + 6*64 + 8*1024) * 4;             //  67,072 B -> 3 blocks/SM
    cudaFuncSetAttribute(precompute_kernel, cudaFuncAttributeMaxDynamicSharedMemorySize, smemA);
    cudaFuncSetAttribute(fused_kernel,      cudaFuncAttributeMaxDynamicSharedMemorySize, smemB);

    precompute_kernel<<<296, 256, smemA>>>(x, ew1, eb1, dw1, db1);
    fused_kernel<<<444, 256, smemB>>>(eidx, edist, ew1, ew2, eb2, ew3, eb3,
                                      dw1, dw2, db2, dw3, db3,
                                      out_w, out_g, out_e, out_k);
}